// round 1
// baseline (speedup 1.0000x reference)
#include <cuda_runtime.h>
#include <math.h>

#define NN 50000
#define NE 400000
#define ET (NE + NN)
#define D 128
#define KU 1664
#define BM 128
#define BN 128
#define BK 16
#define MBLK ((NN + BM - 1) / BM)

// ---------------- scratch (device globals: allocation-free kernel_launch) ----------------
__device__ float g_ac[(size_t)NN * 256];    // [a | c] per node (a=Ws@h, c=Wd@h+Mb)
__device__ float g_agg[(size_t)NN * 512];   // [mx | mn | std | var] per node
__device__ float g_scal[NN * 2];            // logd/4, 4/logd
__device__ float g_u[(size_t)NN * D];       // pre-BN u
__device__ float g_h1[(size_t)NN * D];
__device__ float g_h2[(size_t)NN * D];
__device__ int   g_cnt[NN];
__device__ int   g_rowptr[NN + 1];
__device__ int   g_wofs[NN];
__device__ int   g_srcs[ET];
__device__ float g_colsum[D];
__device__ float g_colsq[D];
__device__ float g_bnscale[D];
__device__ float g_bnshift[D];

// ---------------- packed f32x2 helpers ----------------
__device__ __forceinline__ unsigned long long pack2(float x) {
    unsigned long long r;
    asm("mov.b64 %0, {%1, %1};" : "=l"(r) : "f"(x));
    return r;
}
__device__ __forceinline__ void ffma2(unsigned long long& c, unsigned long long a,
                                      unsigned long long b) {
    asm("fma.rn.f32x2 %0, %1, %2, %0;" : "+l"(c) : "l"(a), "l"(b));
}
__device__ __forceinline__ float2 upk2(unsigned long long v) {
    float2 r;
    asm("mov.b64 {%0, %1}, %2;" : "=f"(r.x), "=f"(r.y) : "l"(v));
    return r;
}
__device__ __forceinline__ const float* pick_h(int sel, const float* feat) {
    return sel == 0 ? feat : (sel == 1 ? g_h1 : g_h2);
}

// 128x128x16 tile microkernel: 8x8 per thread, f32x2 packed along columns.
__device__ __forceinline__ void mm_tile(const float* As, const float* Ws,
                                        unsigned long long acc[8][4], int tx, int ty) {
#pragma unroll
    for (int kk = 0; kk < BK; kk++) {
        unsigned long long b2[4];
#pragma unroll
        for (int j = 0; j < 4; j++)
            b2[j] = *(const unsigned long long*)&Ws[kk * BN + tx * 8 + j * 2];
#pragma unroll
        for (int i = 0; i < 8; i++) {
            unsigned long long a2 = pack2(As[kk * BM + ty * 8 + i]);
#pragma unroll
            for (int j = 0; j < 4; j++) ffma2(acc[i][j], a2, b2[j]);
        }
    }
}

// ---------------- setup kernels ----------------
__global__ void k_init() {
    int i = blockIdx.x * blockDim.x + threadIdx.x;
    if (i < NN) g_cnt[i] = 1;  // self loop
    if (i < D) { g_colsum[i] = 0.f; g_colsq[i] = 0.f; }
}

__global__ void k_hist(const int* __restrict__ dst) {
    int e = blockIdx.x * blockDim.x + threadIdx.x;
    if (e < NE) atomicAdd(&g_cnt[dst[e]], 1);
}

__global__ void k_scan() {
    __shared__ int sd[1024];
    __shared__ int s_run;
    int tid = threadIdx.x;
    if (tid == 0) { s_run = 0; g_rowptr[0] = 0; }
    __syncthreads();
    for (int base = 0; base < NN; base += 1024) {
        int i = base + tid;
        int v = (i < NN) ? g_cnt[i] : 0;
        sd[tid] = v;
        __syncthreads();
        for (int off = 1; off < 1024; off <<= 1) {
            int t = (tid >= off) ? sd[tid - off] : 0;
            __syncthreads();
            sd[tid] += t;
            __syncthreads();
        }
        int inc = sd[tid] + s_run;
        if (i < NN) { g_rowptr[i + 1] = inc; g_wofs[i] = inc - v; }
        __syncthreads();
        if (tid == 1023) s_run += sd[1023];
        __syncthreads();
    }
}

__global__ void k_scatter(const int* __restrict__ src, const int* __restrict__ dst) {
    int i = blockIdx.x * blockDim.x + threadIdx.x;
    if (i >= ET) return;
    int d, s;
    if (i < NE) { d = dst[i]; s = src[i]; }
    else        { d = i - NE; s = d; }
    int p = atomicAdd(&g_wofs[d], 1);
    g_srcs[p] = s;
}

// ---------------- msg GEMM: [a|c] = h @ [Ws|Wd]^T (+Mb on c) ----------------
__global__ __launch_bounds__(256) void k_gemm_msg(int in_sel, const float* __restrict__ feat,
                                                  const float* __restrict__ Mw,
                                                  const float* __restrict__ Mb) {
    const float* h = pick_h(in_sel, feat);
    __shared__ float As[BK * BM];
    __shared__ float Ws[BK * BN];
    int m0 = blockIdx.x * BM;
    int half = blockIdx.y;
    int tid = threadIdx.x, tx = tid & 15, ty = tid >> 4;
    unsigned long long acc[8][4];
#pragma unroll
    for (int i = 0; i < 8; i++)
#pragma unroll
        for (int j = 0; j < 4; j++) acc[i][j] = 0ull;

    for (int k0 = 0; k0 < D; k0 += BK) {
#pragma unroll
        for (int i = 0; i < 2; i++) {
            int q = tid * 2 + i;
            int m = q >> 2;
            int kq = (q & 3) * 4;
            int row = m0 + m;
            float4 v = make_float4(0.f, 0.f, 0.f, 0.f);
            if (row < NN) v = *(const float4*)&h[(size_t)row * D + k0 + kq];
            As[(kq + 0) * BM + m] = v.x;
            As[(kq + 1) * BM + m] = v.y;
            As[(kq + 2) * BM + m] = v.z;
            As[(kq + 3) * BM + m] = v.w;
            float4 w = *(const float4*)&Mw[(size_t)m * 256 + half * 128 + k0 + kq];
            Ws[(kq + 0) * BN + m] = w.x;
            Ws[(kq + 1) * BN + m] = w.y;
            Ws[(kq + 2) * BN + m] = w.z;
            Ws[(kq + 3) * BN + m] = w.w;
        }
        __syncthreads();
        mm_tile(As, Ws, acc, tx, ty);
        __syncthreads();
    }
    float bias[8];
#pragma unroll
    for (int j = 0; j < 8; j++) bias[j] = half ? Mb[tx * 8 + j] : 0.f;
#pragma unroll
    for (int i = 0; i < 8; i++) {
        int row = m0 + ty * 8 + i;
        if (row < NN) {
            float o[8];
#pragma unroll
            for (int j = 0; j < 4; j++) {
                float2 p = upk2(acc[i][j]);
                o[2 * j] = p.x + bias[2 * j];
                o[2 * j + 1] = p.y + bias[2 * j + 1];
            }
            size_t base = (size_t)row * 256 + half * 128 + tx * 8;
            *(float4*)&g_ac[base] = make_float4(o[0], o[1], o[2], o[3]);
            *(float4*)&g_ac[base + 4] = make_float4(o[4], o[5], o[6], o[7]);
        }
    }
}

// ---------------- edge aggregation: 1 warp per node over CSR ----------------
__global__ void k_agg() {
    int gw = (blockIdx.x * blockDim.x + threadIdx.x) >> 5;
    int lane = threadIdx.x & 31;
    if (gw >= NN) return;
    int v = gw;
    int c4 = lane * 4;
    float4 cv = *(const float4*)&g_ac[(size_t)v * 256 + 128 + c4];
    float c[4] = {cv.x, cv.y, cv.z, cv.w};
    float sum[4] = {0.f, 0.f, 0.f, 0.f};
    float sq[4] = {0.f, 0.f, 0.f, 0.f};
    float mx[4] = {-1e30f, -1e30f, -1e30f, -1e30f};
    float mn[4] = {1e30f, 1e30f, 1e30f, 1e30f};
    int e0 = g_rowptr[v], e1 = g_rowptr[v + 1];
    for (int e = e0; e < e1; e++) {
        int s = g_srcs[e];
        float4 av = *(const float4*)&g_ac[(size_t)s * 256 + c4];
        float a[4] = {av.x, av.y, av.z, av.w};
#pragma unroll
        for (int j = 0; j < 4; j++) {
            float m = a[j] + c[j];
            sum[j] += m;
            sq[j] += m * m;
            mx[j] = fmaxf(mx[j], m);
            mn[j] = fminf(mn[j], m);
        }
    }
    float deg = (float)(e1 - e0);
    float inv = 1.f / deg;
    float st[4], vr[4];
#pragma unroll
    for (int j = 0; j < 4; j++) {
        float mean = sum[j] * inv;
        float var = fmaxf(sq[j] * inv - mean * mean, 0.f);
        vr[j] = var;
        st[j] = sqrtf(var + 1e-30f);
    }
    size_t base = (size_t)v * 512 + c4;
    *(float4*)&g_agg[base] = make_float4(mx[0], mx[1], mx[2], mx[3]);
    *(float4*)&g_agg[base + 128] = make_float4(mn[0], mn[1], mn[2], mn[3]);
    *(float4*)&g_agg[base + 256] = make_float4(st[0], st[1], st[2], st[3]);
    *(float4*)&g_agg[base + 384] = make_float4(vr[0], vr[1], vr[2], vr[3]);
    if (lane == 0) {
        float ld = logf(deg + 1.f);
        g_scal[2 * v] = ld * 0.25f;      // logd / DELTA
        g_scal[2 * v + 1] = 4.f / ld;    // DELTA / logd
    }
}

// ---------------- U GEMM: u = ([h | hn] @ Uw^T + Ub) * sqrt(1/N); BN partial sums ----------------
__global__ __launch_bounds__(256) void k_ugemm(int in_sel, const float* __restrict__ feat,
                                               const float* __restrict__ Uw,
                                               const float* __restrict__ Ub) {
    const float* h = pick_h(in_sel, feat);
    __shared__ float pool[4352];  // As(2048) | Ws(2048) during GEMM, then 2x 128*17 partials
    __shared__ float slog_s[BM], sinv_s[BM];
    float* As = pool;
    float* Ws = pool + BK * BM;
    int m0 = blockIdx.x * BM;
    int tid = threadIdx.x, tx = tid & 15, ty = tid >> 4;
    if (tid < BM) {
        int r = m0 + tid;
        slog_s[tid] = (r < NN) ? g_scal[2 * r] : 0.f;
        sinv_s[tid] = (r < NN) ? g_scal[2 * r + 1] : 0.f;
    }
    __syncthreads();
    unsigned long long acc[8][4];
#pragma unroll
    for (int i = 0; i < 8; i++)
#pragma unroll
        for (int j = 0; j < 4; j++) acc[i][j] = 0ull;

    for (int k0 = 0; k0 < KU; k0 += BK) {
        int regionH = (k0 < D);
        int off = k0 - D;
        int g = off >> 9;
        int j0 = off & 511;
#pragma unroll
        for (int i = 0; i < 2; i++) {
            int q = tid * 2 + i;
            int m = q >> 2;
            int kq = (q & 3) * 4;
            int row = m0 + m;
            float4 v = make_float4(0.f, 0.f, 0.f, 0.f);
            if (row < NN) {
                if (regionH) {
                    v = *(const float4*)&h[(size_t)row * D + k0 + kq];
                } else {
                    v = *(const float4*)&g_agg[(size_t)row * 512 + j0 + kq];
                    float s = (g == 0) ? 1.f : (g == 1 ? slog_s[m] : sinv_s[m]);
                    v.x *= s; v.y *= s; v.z *= s; v.w *= s;
                }
            }
            As[(kq + 0) * BM + m] = v.x;
            As[(kq + 1) * BM + m] = v.y;
            As[(kq + 2) * BM + m] = v.z;
            As[(kq + 3) * BM + m] = v.w;
            float4 w = *(const float4*)&Uw[(size_t)m * KU + k0 + kq];
            Ws[(kq + 0) * BN + m] = w.x;
            Ws[(kq + 1) * BN + m] = w.y;
            Ws[(kq + 2) * BN + m] = w.z;
            Ws[(kq + 3) * BN + m] = w.w;
        }
        __syncthreads();
        mm_tile(As, Ws, acc, tx, ty);
        __syncthreads();
    }
    const float RSQN = 0.004472135954999579f;  // sqrt(1/50000)
    float ub[8];
#pragma unroll
    for (int j = 0; j < 8; j++) ub[j] = Ub[tx * 8 + j];
    float csum[8], csq[8];
#pragma unroll
    for (int j = 0; j < 8; j++) { csum[j] = 0.f; csq[j] = 0.f; }
#pragma unroll
    for (int i = 0; i < 8; i++) {
        int row = m0 + ty * 8 + i;
        float o[8];
#pragma unroll
        for (int j = 0; j < 4; j++) {
            float2 p = upk2(acc[i][j]);
            o[2 * j] = (p.x + ub[2 * j]) * RSQN;
            o[2 * j + 1] = (p.y + ub[2 * j + 1]) * RSQN;
        }
        if (row < NN) {
            size_t base = (size_t)row * D + tx * 8;
            *(float4*)&g_u[base] = make_float4(o[0], o[1], o[2], o[3]);
            *(float4*)&g_u[base + 4] = make_float4(o[4], o[5], o[6], o[7]);
#pragma unroll
            for (int j = 0; j < 8; j++) {
                csum[j] += o[j];
                csq[j] += o[j] * o[j];
            }
        }
    }
    float* psum = pool;
    float* psq = pool + 128 * 17;
#pragma unroll
    for (int j = 0; j < 8; j++) {
        psum[(tx * 8 + j) * 17 + ty] = csum[j];
        psq[(tx * 8 + j) * 17 + ty] = csq[j];
    }
    __syncthreads();
    if (tid < D) {
        float s = 0.f, q = 0.f;
        for (int t = 0; t < 16; t++) {
            s += psum[tid * 17 + t];
            q += psq[tid * 17 + t];
        }
        atomicAdd(&g_colsum[tid], s);
        atomicAdd(&g_colsq[tid], q);
    }
}

// ---------------- BN finalize: fold mu/var/gamma/beta into scale+shift ----------------
__global__ void k_bnfinal(const float* __restrict__ bng, const float* __restrict__ bnb) {
    int c = threadIdx.x;
    if (c < D) {
        float mu = g_colsum[c] * (1.f / NN);
        float var = g_colsq[c] * (1.f / NN) - mu * mu;
        float inv = rsqrtf(var + 1e-5f);
        float sc = inv * bng[c];
        g_bnscale[c] = sc;
        g_bnshift[c] = bnb[c] - mu * sc;
        g_colsum[c] = 0.f;   // ready for next layer
        g_colsq[c] = 0.f;
    }
}

// ---------------- mix GEMM + leaky + residual + LayerNorm + ELU ----------------
__global__ __launch_bounds__(256) void k_mixln(int in_sel, const float* __restrict__ feat,
                                               const float* __restrict__ Mixw,
                                               const float* __restrict__ Mixb,
                                               const float* __restrict__ Lng,
                                               const float* __restrict__ Lnb,
                                               int out_sel, float* __restrict__ dout) {
    const float* hin = pick_h(in_sel, feat);
    float* hout = (out_sel == 1) ? g_h1 : (out_sel == 2 ? g_h2 : dout);
    __shared__ float pool[4352];
    __shared__ float bs_s[D], bh_s[D];
    __shared__ float mu_s[BM], rs_s[BM];
    float* As = pool;
    float* Ws = pool + BK * BM;
    int m0 = blockIdx.x * BM;
    int tid = threadIdx.x, tx = tid & 15, ty = tid >> 4;
    if (tid < D) { bs_s[tid] = g_bnscale[tid]; bh_s[tid] = g_bnshift[tid]; }
    __syncthreads();
    unsigned long long acc[8][4];
#pragma unroll
    for (int i = 0; i < 8; i++)
#pragma unroll
        for (int j = 0; j < 4; j++) acc[i][j] = 0ull;

    for (int k0 = 0; k0 < D; k0 += BK) {
#pragma unroll
        for (int i = 0; i < 2; i++) {
            int q = tid * 2 + i;
            int m = q >> 2;
            int kq = (q & 3) * 4;
            int row = m0 + m;
            float4 v = make_float4(0.f, 0.f, 0.f, 0.f);
            if (row < NN) {
                v = *(const float4*)&g_u[(size_t)row * D + k0 + kq];
                v.x = v.x * bs_s[k0 + kq + 0] + bh_s[k0 + kq + 0];
                v.y = v.y * bs_s[k0 + kq + 1] + bh_s[k0 + kq + 1];
                v.z = v.z * bs_s[k0 + kq + 2] + bh_s[k0 + kq + 2];
                v.w = v.w * bs_s[k0 + kq + 3] + bh_s[k0 + kq + 3];
            }
            As[(kq + 0) * BM + m] = v.x;
            As[(kq + 1) * BM + m] = v.y;
            As[(kq + 2) * BM + m] = v.z;
            As[(kq + 3) * BM + m] = v.w;
            float4 w = *(const float4*)&Mixw[(size_t)m * D + k0 + kq];
            Ws[(kq + 0) * BN + m] = w.x;
            Ws[(kq + 1) * BN + m] = w.y;
            Ws[(kq + 2) * BN + m] = w.z;
            Ws[(kq + 3) * BN + m] = w.w;
        }
        __syncthreads();
        mm_tile(As, Ws, acc, tx, ty);
        __syncthreads();
    }
    float y[8][8];
    {
        float mb[8];
#pragma unroll
        for (int j = 0; j < 8; j++) mb[j] = Mixb[tx * 8 + j];
#pragma unroll
        for (int i = 0; i < 8; i++) {
#pragma unroll
            for (int j = 0; j < 4; j++) {
                float2 p = upk2(acc[i][j]);
                y[i][2 * j] = p.x + mb[2 * j];
                y[i][2 * j + 1] = p.y + mb[2 * j + 1];
            }
#pragma unroll
            for (int j = 0; j < 8; j++) {
                float t = y[i][j];
                y[i][j] = fmaxf(t, 0.01f * t);  // leaky relu
            }
            int row = m0 + ty * 8 + i;
            if (row < NN) {  // residual
                float4 h0 = *(const float4*)&hin[(size_t)row * D + tx * 8];
                float4 h1 = *(const float4*)&hin[(size_t)row * D + tx * 8 + 4];
                y[i][0] += h0.x; y[i][1] += h0.y; y[i][2] += h0.z; y[i][3] += h0.w;
                y[i][4] += h1.x; y[i][5] += h1.y; y[i][6] += h1.z; y[i][7] += h1.w;
            }
        }
    }
    // row-wise LayerNorm partials (reuse pool)
    float* psum = pool;
    float* psq = pool + 128 * 17;
#pragma unroll
    for (int i = 0; i < 8; i++) {
        float s = 0.f, q = 0.f;
#pragma unroll
        for (int j = 0; j < 8; j++) {
            s += y[i][j];
            q += y[i][j] * y[i][j];
        }
        psum[(ty * 8 + i) * 17 + tx] = s;
        psq[(ty * 8 + i) * 17 + tx] = q;
    }
    __syncthreads();
    if (tid < BM) {
        float s = 0.f, q = 0.f;
        for (int t = 0; t < 16; t++) {
            s += psum[tid * 17 + t];
            q += psq[tid * 17 + t];
        }
        float mu = s * (1.f / D);
        float var = q * (1.f / D) - mu * mu;
        mu_s[tid] = mu;
        rs_s[tid] = rsqrtf(var + 1e-5f);
    }
    __syncthreads();
    float lg[8], lb[8];
#pragma unroll
    for (int j = 0; j < 8; j++) {
        lg[j] = Lng[tx * 8 + j];
        lb[j] = Lnb[tx * 8 + j];
    }
#pragma unroll
    for (int i = 0; i < 8; i++) {
        int r = ty * 8 + i;
        int row = m0 + r;
        if (row < NN) {
            float mu = mu_s[r], rs = rs_s[r];
            float o[8];
#pragma unroll
            for (int j = 0; j < 8; j++) {
                float v = (y[i][j] - mu) * rs * lg[j] + lb[j];
                o[j] = (v > 0.f) ? v : expm1f(v);  // elu
            }
            size_t base = (size_t)row * D + tx * 8;
            *(float4*)&hout[base] = make_float4(o[0], o[1], o[2], o[3]);
            *(float4*)&hout[base + 4] = make_float4(o[4], o[5], o[6], o[7]);
        }
    }
}

// ---------------- launch ----------------
extern "C" void kernel_launch(void* const* d_in, const int* in_sizes, int n_in,
                              void* d_out, int out_size) {
    const float* feat = (const float*)d_in[0];
    const int* src = (const int*)d_in[1];
    const int* dst = (const int*)d_in[2];
    const float* Mw = (const float*)d_in[3];
    const float* Mb = (const float*)d_in[4];
    const float* Uw = (const float*)d_in[5];
    const float* Ub = (const float*)d_in[6];
    const float* bn_g = (const float*)d_in[7];
    const float* bn_b = (const float*)d_in[8];
    const float* mix_w = (const float*)d_in[9];
    const float* mix_b = (const float*)d_in[10];
    const float* ln_g = (const float*)d_in[11];
    const float* ln_b = (const float*)d_in[12];

    k_init<<<(NN + 255) / 256, 256>>>();
    k_hist<<<(NE + 255) / 256, 256>>>(dst);
    k_scan<<<1, 1024>>>();
    k_scatter<<<(ET + 255) / 256, 256>>>(src, dst);

    for (int l = 0; l < 3; l++) {
        int isel = (l == 0) ? 0 : l;          // 0=feat, 1=g_h1, 2=g_h2
        int osel = (l == 2) ? 3 : (l + 1);    // 1=g_h1, 2=g_h2, 3=d_out
        const float* Mw_l = Mw + (size_t)l * D * 2 * D;
        const float* Mb_l = Mb + (size_t)l * D;
        const float* Uw_l = Uw + (size_t)l * D * KU;
        const float* Ub_l = Ub + (size_t)l * D;

        k_gemm_msg<<<dim3(MBLK, 2), 256>>>(isel, feat, Mw_l, Mb_l);
        k_agg<<<(NN * 32 + 255) / 256, 256>>>();
        k_ugemm<<<MBLK, 256>>>(isel, feat, Uw_l, Ub_l);
        k_bnfinal<<<1, 128>>>(bn_g + (size_t)l * D, bn_b + (size_t)l * D);
        k_mixln<<<MBLK, 256>>>(isel, feat, mix_w + (size_t)l * D * D,
                               mix_b + (size_t)l * D, ln_g + (size_t)l * D,
                               ln_b + (size_t)l * D, osel, (float*)d_out);
    }
}

// round 5
// speedup vs baseline: 1.4814x; 1.4814x over previous
#include <cuda_runtime.h>
#include <cuda_bf16.h>
#include <stdint.h>
#include <math.h>

#define NN 50000
#define NE 400000
#define ET (NE + NN)
#define D 128
#define KU 1664
#define BM 128
#define BN 128
#define BK 16
#define MBLK ((NN + BM - 1) / BM)   // 391; 391*128 = 50048
#define NPAD 50048
#define KC 32                        // K-chunk for mma kernel
#define NC (KU / KC)                 // 52
#define TS 40                        // smem row stride in bf16 (32 + 8 pad)
#define TILE (128 * TS)              // 5120 bf16 per tile
#define STG (4 * TILE)               // 20480 bf16 per stage (XH,XL,WH,WL)

// ---------------- scratch ----------------
__device__ float g_ac[(size_t)NN * 256];    // [a | c] per node
__device__ float g_u[(size_t)NN * D];       // pre-BN u
__device__ float g_h1[(size_t)NN * D];
__device__ float g_h2[(size_t)NN * D];
__device__ __nv_bfloat16 g_xhi[(size_t)NPAD * KU];  // X = [h | agg | agg*s1 | agg*s2] hi
__device__ __nv_bfloat16 g_xlo[(size_t)NPAD * KU];  // lo
__device__ __nv_bfloat16 g_whi[(size_t)3 * D * KU]; // Uw split hi
__device__ __nv_bfloat16 g_wlo[(size_t)3 * D * KU];
__device__ int   g_cnt[NN];
__device__ int   g_rowptr[NN + 1];
__device__ int   g_wofs[NN];
__device__ int   g_srcs[ET];
__device__ float g_colsum[D];
__device__ float g_colsq[D];
__device__ float g_bnscale[D];
__device__ float g_bnshift[D];

// ---------------- PTX helpers ----------------
__device__ __forceinline__ uint32_t smem_u32(const void* p) {
    uint32_t a;
    asm("{ .reg .u64 t; cvta.to.shared.u64 t, %1; cvt.u32.u64 %0, t; }" : "=r"(a) : "l"(p));
    return a;
}
__device__ __forceinline__ void cpa16(uint32_t s, const void* g) {
    asm volatile("cp.async.cg.shared.global [%0], [%1], 16;" :: "r"(s), "l"(g) : "memory");
}
__device__ __forceinline__ void ldm4(uint32_t a, uint32_t* r) {
    asm volatile("ldmatrix.sync.aligned.m8n8.x4.shared.b16 {%0,%1,%2,%3}, [%4];"
                 : "=r"(r[0]), "=r"(r[1]), "=r"(r[2]), "=r"(r[3]) : "r"(a));
}
__device__ __forceinline__ void mma16816(float* c, const uint32_t* a, const uint32_t* b) {
    asm volatile("mma.sync.aligned.m16n8k16.row.col.f32.bf16.bf16.f32 "
                 "{%0,%1,%2,%3}, {%4,%5,%6,%7}, {%8,%9}, {%0,%1,%2,%3};"
                 : "+f"(c[0]), "+f"(c[1]), "+f"(c[2]), "+f"(c[3])
                 : "r"(a[0]), "r"(a[1]), "r"(a[2]), "r"(a[3]), "r"(b[0]), "r"(b[1]));
}

// ---------------- bf16 split ----------------
struct __align__(8) bfq { __nv_bfloat162 a, b; };
__device__ __forceinline__ void split_store4(float x0, float x1, float x2, float x3,
                                             __nv_bfloat16* hp, __nv_bfloat16* lp) {
    __nv_bfloat162 h0 = __floats2bfloat162_rn(x0, x1);
    __nv_bfloat162 h1 = __floats2bfloat162_rn(x2, x3);
    __nv_bfloat162 l0 = __floats2bfloat162_rn(x0 - __low2float(h0), x1 - __high2float(h0));
    __nv_bfloat162 l1 = __floats2bfloat162_rn(x2 - __low2float(h1), x3 - __high2float(h1));
    bfq h; h.a = h0; h.b = h1;
    bfq l; l.a = l0; l.b = l1;
    *(bfq*)hp = h;
    *(bfq*)lp = l;
}

// ---------------- packed f32x2 helpers (SIMT GEMMs) ----------------
__device__ __forceinline__ unsigned long long pack2(float x) {
    unsigned long long r;
    asm("mov.b64 %0, {%1, %1};" : "=l"(r) : "f"(x));
    return r;
}
__device__ __forceinline__ void ffma2(unsigned long long& c, unsigned long long a,
                                      unsigned long long b) {
    asm("fma.rn.f32x2 %0, %1, %2, %0;" : "+l"(c) : "l"(a), "l"(b));
}
__device__ __forceinline__ float2 upk2(unsigned long long v) {
    float2 r;
    asm("mov.b64 {%0, %1}, %2;" : "=f"(r.x), "=f"(r.y) : "l"(v));
    return r;
}
__device__ __forceinline__ const float* pick_h(int sel, const float* feat) {
    return sel == 0 ? feat : (sel == 1 ? g_h1 : g_h2);
}

__device__ __forceinline__ void mm_tile(const float* As, const float* Ws,
                                        unsigned long long acc[8][4], int tx, int ty) {
#pragma unroll
    for (int kk = 0; kk < BK; kk++) {
        unsigned long long b2[4];
#pragma unroll
        for (int j = 0; j < 4; j++)
            b2[j] = *(const unsigned long long*)&Ws[kk * BN + tx * 8 + j * 2];
#pragma unroll
        for (int i = 0; i < 8; i++) {
            unsigned long long a2 = pack2(As[kk * BM + ty * 8 + i]);
#pragma unroll
            for (int j = 0; j < 4; j++) ffma2(acc[i][j], a2, b2[j]);
        }
    }
}

// ---------------- setup kernels ----------------
__global__ void k_init() {
    int i = blockIdx.x * blockDim.x + threadIdx.x;
    if (i < NN) g_cnt[i] = 1;
    if (i < D) { g_colsum[i] = 0.f; g_colsq[i] = 0.f; }
}

__global__ void k_hist(const int* __restrict__ dst) {
    int e = blockIdx.x * blockDim.x + threadIdx.x;
    if (e < NE) atomicAdd(&g_cnt[dst[e]], 1);
}

__global__ void k_scan() {
    __shared__ int sd[1024];
    __shared__ int s_run;
    int tid = threadIdx.x;
    if (tid == 0) { s_run = 0; g_rowptr[0] = 0; }
    __syncthreads();
    for (int base = 0; base < NN; base += 1024) {
        int i = base + tid;
        int v = (i < NN) ? g_cnt[i] : 0;
        sd[tid] = v;
        __syncthreads();
        for (int off = 1; off < 1024; off <<= 1) {
            int t = (tid >= off) ? sd[tid - off] : 0;
            __syncthreads();
            sd[tid] += t;
            __syncthreads();
        }
        int inc = sd[tid] + s_run;
        if (i < NN) { g_rowptr[i + 1] = inc; g_wofs[i] = inc - v; }
        __syncthreads();
        if (tid == 1023) s_run += sd[1023];
        __syncthreads();
    }
}

__global__ void k_scatter(const int* __restrict__ src, const int* __restrict__ dst) {
    int i = blockIdx.x * blockDim.x + threadIdx.x;
    if (i >= ET) return;
    int d, s;
    if (i < NE) { d = dst[i]; s = src[i]; }
    else        { d = i - NE; s = d; }
    int p = atomicAdd(&g_wofs[d], 1);
    g_srcs[p] = s;
}

__global__ void k_split_feat(const float* __restrict__ feat) {
    int i = blockIdx.x * blockDim.x + threadIdx.x;
    if (i >= NN * 32) return;
    int r = i >> 5;
    int c = (i & 31) * 4;
    float4 v = *(const float4*)&feat[(size_t)r * D + c];
    split_store4(v.x, v.y, v.z, v.w, &g_xhi[(size_t)r * KU + c], &g_xlo[(size_t)r * KU + c]);
}

__global__ void k_split_w(const float* __restrict__ Uw) {
    int i = blockIdx.x * blockDim.x + threadIdx.x;
    if (i >= 3 * D * KU / 4) return;
    size_t o = (size_t)i * 4;
    float4 v = *(const float4*)&Uw[o];
    split_store4(v.x, v.y, v.z, v.w, &g_whi[o], &g_wlo[o]);
}

// ---------------- msg GEMM (SIMT): [a|c] = h @ [Ws|Wd]^T (+Mb on c) ----------------
__global__ __launch_bounds__(256) void k_gemm_msg(int in_sel, const float* __restrict__ feat,
                                                  const float* __restrict__ Mw,
                                                  const float* __restrict__ Mb) {
    const float* h = pick_h(in_sel, feat);
    __shared__ float As[BK * BM];
    __shared__ float Ws[BK * BN];
    int m0 = blockIdx.x * BM;
    int half = blockIdx.y;
    int tid = threadIdx.x, tx = tid & 15, ty = tid >> 4;
    unsigned long long acc[8][4];
#pragma unroll
    for (int i = 0; i < 8; i++)
#pragma unroll
        for (int j = 0; j < 4; j++) acc[i][j] = 0ull;

    for (int k0 = 0; k0 < D; k0 += BK) {
#pragma unroll
        for (int i = 0; i < 2; i++) {
            int q = tid * 2 + i;
            int m = q >> 2;
            int kq = (q & 3) * 4;
            int row = m0 + m;
            float4 v = make_float4(0.f, 0.f, 0.f, 0.f);
            if (row < NN) v = *(const float4*)&h[(size_t)row * D + k0 + kq];
            As[(kq + 0) * BM + m] = v.x;
            As[(kq + 1) * BM + m] = v.y;
            As[(kq + 2) * BM + m] = v.z;
            As[(kq + 3) * BM + m] = v.w;
            float4 w = *(const float4*)&Mw[(size_t)m * 256 + half * 128 + k0 + kq];
            Ws[(kq + 0) * BN + m] = w.x;
            Ws[(kq + 1) * BN + m] = w.y;
            Ws[(kq + 2) * BN + m] = w.z;
            Ws[(kq + 3) * BN + m] = w.w;
        }
        __syncthreads();
        mm_tile(As, Ws, acc, tx, ty);
        __syncthreads();
    }
    float bias[8];
#pragma unroll
    for (int j = 0; j < 8; j++) bias[j] = half ? Mb[tx * 8 + j] : 0.f;
#pragma unroll
    for (int i = 0; i < 8; i++) {
        int row = m0 + ty * 8 + i;
        if (row < NN) {
            float o[8];
#pragma unroll
            for (int j = 0; j < 4; j++) {
                float2 p = upk2(acc[i][j]);
                o[2 * j] = p.x + bias[2 * j];
                o[2 * j + 1] = p.y + bias[2 * j + 1];
            }
            size_t base = (size_t)row * 256 + half * 128 + tx * 8;
            *(float4*)&g_ac[base] = make_float4(o[0], o[1], o[2], o[3]);
            *(float4*)&g_ac[base + 4] = make_float4(o[4], o[5], o[6], o[7]);
        }
    }
}

// ---------------- edge aggregation: 1 warp per node; emits bf16 hi/lo X cols 128..1663 ----------------
__global__ void k_agg() {
    int gw = (blockIdx.x * blockDim.x + threadIdx.x) >> 5;
    int lane = threadIdx.x & 31;
    if (gw >= NN) return;
    int v = gw;
    int c4 = lane * 4;
    float4 cv = *(const float4*)&g_ac[(size_t)v * 256 + 128 + c4];
    float c[4] = {cv.x, cv.y, cv.z, cv.w};
    float sum[4] = {0.f, 0.f, 0.f, 0.f};
    float sq[4] = {0.f, 0.f, 0.f, 0.f};
    float mx[4] = {-1e30f, -1e30f, -1e30f, -1e30f};
    float mn[4] = {1e30f, 1e30f, 1e30f, 1e30f};
    int e0 = g_rowptr[v], e1 = g_rowptr[v + 1];
    for (int e = e0; e < e1; e++) {
        int s = g_srcs[e];
        float4 av = *(const float4*)&g_ac[(size_t)s * 256 + c4];
        float a[4] = {av.x, av.y, av.z, av.w};
#pragma unroll
        for (int j = 0; j < 4; j++) {
            float m = a[j] + c[j];
            sum[j] += m;
            sq[j] += m * m;
            mx[j] = fmaxf(mx[j], m);
            mn[j] = fminf(mn[j], m);
        }
    }
    float deg = (float)(e1 - e0);
    float inv = 1.f / deg;
    float st[4], vr[4];
#pragma unroll
    for (int j = 0; j < 4; j++) {
        float mean = sum[j] * inv;
        float var = fmaxf(sq[j] * inv - mean * mean, 0.f);
        vr[j] = var;
        st[j] = sqrtf(var + 1e-30f);
    }
    float ld = logf(deg + 1.f);
    float s1v = ld * 0.25f;
    float s2v = 4.f / ld;
    size_t xb = (size_t)v * KU;
#pragma unroll
    for (int g = 0; g < 3; g++) {
        float sc = (g == 0) ? 1.f : (g == 1 ? s1v : s2v);
        int base = 128 + g * 512 + c4;
        split_store4(mx[0] * sc, mx[1] * sc, mx[2] * sc, mx[3] * sc,
                     &g_xhi[xb + base], &g_xlo[xb + base]);
        split_store4(mn[0] * sc, mn[1] * sc, mn[2] * sc, mn[3] * sc,
                     &g_xhi[xb + base + 128], &g_xlo[xb + base + 128]);
        split_store4(st[0] * sc, st[1] * sc, st[2] * sc, st[3] * sc,
                     &g_xhi[xb + base + 256], &g_xlo[xb + base + 256]);
        split_store4(vr[0] * sc, vr[1] * sc, vr[2] * sc, vr[3] * sc,
                     &g_xhi[xb + base + 384], &g_xlo[xb + base + 384]);
    }
}

// ---------------- U GEMM on mma.sync bf16 (3-term hi/lo split) ----------------
// u = (X @ Uw^T + Ub) * sqrt(1/N), X:[NPAD,KU] bf16 hi/lo, Uw:[D,KU] bf16 hi/lo
__global__ __launch_bounds__(256) void k_ugemm_mma(int layer, const float* __restrict__ Ub) {
    extern __shared__ __nv_bfloat16 sm[];
    int tid = threadIdx.x, wid = tid >> 5, l = tid & 31;
    int wm = wid >> 1, wn = wid & 1;       // warp grid 4(M) x 2(N); warp tile 32x64
    int m0 = blockIdx.x * BM;
    uint32_t smb = smem_u32(sm);

    const __nv_bfloat16* axh = g_xhi + (size_t)m0 * KU;
    const __nv_bfloat16* axl = g_xlo + (size_t)m0 * KU;
    const __nv_bfloat16* bwh = g_whi + (size_t)layer * D * KU;
    const __nv_bfloat16* bwl = g_wlo + (size_t)layer * D * KU;

    float acc[2][2][4][4];
#pragma unroll
    for (int a = 0; a < 2; a++)
#pragma unroll
        for (int b = 0; b < 2; b++)
#pragma unroll
            for (int cidx = 0; cidx < 4; cidx++)
#pragma unroll
                for (int d = 0; d < 4; d++) acc[a][b][cidx][d] = 0.f;

    // per-thread load geometry (2 x uint4 per tile per chunk)
    int lr0 = tid >> 2, lq0 = tid & 3;

    // prefetch chunk 0
    {
        int kg = 0;
        uint32_t sb = smb;
#pragma unroll
        for (int t2 = 0; t2 < 2; t2++) {
            int row = lr0 + t2 * 64;
            size_t go = (size_t)row * KU + kg + lq0 * 8;
            uint32_t so = sb + (row * TS + lq0 * 8) * 2;
            cpa16(so, axh + go);
            cpa16(so + TILE * 2, axl + go);
            cpa16(so + 2 * TILE * 2, bwh + go);
            cpa16(so + 3 * TILE * 2, bwl + go);
        }
        asm volatile("cp.async.commit_group;" ::: "memory");
    }

    for (int c = 0; c < NC; c++) {
        asm volatile("cp.async.wait_group 0;" ::: "memory");
        __syncthreads();
        if (c + 1 < NC) {
            int kg = (c + 1) * KC;
            uint32_t sb = smb + ((c + 1) & 1) * (STG * 2);
#pragma unroll
            for (int t2 = 0; t2 < 2; t2++) {
                int row = lr0 + t2 * 64;
                size_t go = (size_t)row * KU + kg + lq0 * 8;
                uint32_t so = sb + (row * TS + lq0 * 8) * 2;
                cpa16(so, axh + go);
                cpa16(so + TILE * 2, axl + go);
                cpa16(so + 2 * TILE * 2, bwh + go);
                cpa16(so + 3 * TILE * 2, bwl + go);
            }
            asm volatile("cp.async.commit_group;" ::: "memory");
        }
        uint32_t st = smb + (c & 1) * (STG * 2);
#pragma unroll
        for (int kk = 0; kk < 2; kk++) {
            int k16 = kk * 16;
            uint32_t ah[2][4], al[2][4];
#pragma unroll
            for (int mf = 0; mf < 2; mf++) {
                int arow = wm * 32 + mf * 16 + (l & 7) + ((l >> 3) & 1) * 8;
                uint32_t ao = st + (arow * TS + k16 + (l >> 4) * 8) * 2;
                ldm4(ao, ah[mf]);
                ldm4(ao + TILE * 2, al[mf]);
            }
#pragma unroll
            for (int nh = 0; nh < 2; nh++) {
                uint32_t bh[2][4], bl[2][4];
#pragma unroll
                for (int g16 = 0; g16 < 2; g16++) {
                    int brow = wn * 64 + nh * 32 + g16 * 16 + (l & 7) + (l >> 4) * 8;
                    uint32_t bo = st + 2 * TILE * 2 + (brow * TS + k16 + ((l >> 3) & 1) * 8) * 2;
                    ldm4(bo, bh[g16]);
                    ldm4(bo + TILE * 2, bl[g16]);
                }
#pragma unroll
                for (int mf = 0; mf < 2; mf++)
#pragma unroll
                    for (int g16 = 0; g16 < 2; g16++)
#pragma unroll
                        for (int f = 0; f < 2; f++) {
                            float* c4p = acc[mf][nh][g16 * 2 + f];
                            mma16816(c4p, ah[mf], &bh[g16][f * 2]);   // hi*hi
                            mma16816(c4p, ah[mf], &bl[g16][f * 2]);   // hi*lo
                            mma16816(c4p, al[mf], &bh[g16][f * 2]);   // lo*hi
                        }
            }
        }
    }

    const float RSQN = 0.004472135954999579f;  // sqrt(1/50000)
    int grp = l >> 2, tig = l & 3;
#pragma unroll
    for (int mf = 0; mf < 2; mf++) {
        int r0 = m0 + wm * 32 + mf * 16 + grp;
#pragma unroll
        for (int nh = 0; nh < 2; nh++)
#pragma unroll
            for (int nf = 0; nf < 4; nf++) {
                int col = wn * 64 + nh * 32 + nf * 8 + tig * 2;
                float u0 = Ub[col], u1 = Ub[col + 1];
                float* a4 = acc[mf][nh][nf];
                if (r0 < NN)
                    *(float2*)&g_u[(size_t)r0 * D + col] =
                        make_float2((a4[0] + u0) * RSQN, (a4[1] + u1) * RSQN);
                if (r0 + 8 < NN)
                    *(float2*)&g_u[(size_t)(r0 + 8) * D + col] =
                        make_float2((a4[2] + u0) * RSQN, (a4[3] + u1) * RSQN);
            }
    }
}

// ---------------- BN column stats over g_u ----------------
__global__ void k_bnstats() {
    int col = threadIdx.x & 127;
    int sub = threadIdx.x >> 7;
    float s = 0.f, q = 0.f;
    for (int r = blockIdx.x * 2 + sub; r < NN; r += gridDim.x * 2) {
        float v = g_u[(size_t)r * D + col];
        s += v;
        q += v * v;
    }
    __shared__ float sh[256], shq[256];
    sh[threadIdx.x] = s;
    shq[threadIdx.x] = q;
    __syncthreads();
    if (sub == 0) {
        atomicAdd(&g_colsum[col], s + sh[128 + col]);
        atomicAdd(&g_colsq[col], q + shq[128 + col]);
    }
}

__global__ void k_bnfinal(const float* __restrict__ bng, const float* __restrict__ bnb) {
    int c = threadIdx.x;
    if (c < D) {
        float mu = g_colsum[c] * (1.f / NN);
        float var = g_colsq[c] * (1.f / NN) - mu * mu;
        float inv = rsqrtf(var + 1e-5f);
        float sc = inv * bng[c];
        g_bnscale[c] = sc;
        g_bnshift[c] = bnb[c] - mu * sc;
        g_colsum[c] = 0.f;
        g_colsq[c] = 0.f;
    }
}

// ---------------- mix GEMM + leaky + residual + LayerNorm + ELU (+ X h-cols) ----------------
__global__ __launch_bounds__(256) void k_mixln(int in_sel, const float* __restrict__ feat,
                                               const float* __restrict__ Mixw,
                                               const float* __restrict__ Mixb,
                                               const float* __restrict__ Lng,
                                               const float* __restrict__ Lnb,
                                               int out_sel, float* __restrict__ dout,
                                               int write_x) {
    const float* hin = pick_h(in_sel, feat);
    float* hout = (out_sel == 1) ? g_h1 : (out_sel == 2 ? g_h2 : dout);
    __shared__ float pool[4352];
    __shared__ float bs_s[D], bh_s[D];
    __shared__ float mu_s[BM], rs_s[BM];
    float* As = pool;
    float* Ws = pool + BK * BM;
    int m0 = blockIdx.x * BM;
    int tid = threadIdx.x, tx = tid & 15, ty = tid >> 4;
    if (tid < D) { bs_s[tid] = g_bnscale[tid]; bh_s[tid] = g_bnshift[tid]; }
    __syncthreads();
    unsigned long long acc[8][4];
#pragma unroll
    for (int i = 0; i < 8; i++)
#pragma unroll
        for (int j = 0; j < 4; j++) acc[i][j] = 0ull;

    for (int k0 = 0; k0 < D; k0 += BK) {
#pragma unroll
        for (int i = 0; i < 2; i++) {
            int q = tid * 2 + i;
            int m = q >> 2;
            int kq = (q & 3) * 4;
            int row = m0 + m;
            float4 v = make_float4(0.f, 0.f, 0.f, 0.f);
            if (row < NN) {
                v = *(const float4*)&g_u[(size_t)row * D + k0 + kq];
                v.x = v.x * bs_s[k0 + kq + 0] + bh_s[k0 + kq + 0];
                v.y = v.y * bs_s[k0 + kq + 1] + bh_s[k0 + kq + 1];
                v.z = v.z * bs_s[k0 + kq + 2] + bh_s[k0 + kq + 2];
                v.w = v.w * bs_s[k0 + kq + 3] + bh_s[k0 + kq + 3];
            }
            As[(kq + 0) * BM + m] = v.x;
            As[(kq + 1) * BM + m] = v.y;
            As[(kq + 2) * BM + m] = v.z;
            As[(kq + 3) * BM + m] = v.w;
            float4 w = *(const float4*)&Mixw[(size_t)m * D + k0 + kq];
            Ws[(kq + 0) * BN + m] = w.x;
            Ws[(kq + 1) * BN + m] = w.y;
            Ws[(kq + 2) * BN + m] = w.z;
            Ws[(kq + 3) * BN + m] = w.w;
        }
        __syncthreads();
        mm_tile(As, Ws, acc, tx, ty);
        __syncthreads();
    }
    float y[8][8];
    {
        float mb[8];
#pragma unroll
        for (int j = 0; j < 8; j++) mb[j] = Mixb[tx * 8 + j];
#pragma unroll
        for (int i = 0; i < 8; i++) {
#pragma unroll
            for (int j = 0; j < 4; j++) {
                float2 p = upk2(acc[i][j]);
                y[i][2 * j] = p.x + mb[2 * j];
                y[i][2 * j + 1] = p.y + mb[2 * j + 1];
            }
#pragma unroll
            for (int j = 0; j < 8; j++) {
                float t = y[i][j];
                y[i][j] = fmaxf(t, 0.01f * t);
            }
            int row = m0 + ty * 8 + i;
            if (row < NN) {
                float4 h0 = *(const float4*)&hin[(size_t)row * D + tx * 8];
                float4 h1 = *(const float4*)&hin[(size_t)row * D + tx * 8 + 4];
                y[i][0] += h0.x; y[i][1] += h0.y; y[i][2] += h0.z; y[i][3] += h0.w;
                y[i][4] += h1.x; y[i][5] += h1.y; y[i][6] += h1.z; y[i][7] += h1.w;
            }
        }
    }
    float* psum = pool;
    float* psq = pool + 128 * 17;
#pragma unroll
    for (int i = 0; i < 8; i++) {
        float s = 0.f, q = 0.f;
#pragma unroll
        for (int j = 0; j < 8; j++) {
            s += y[i][j];
            q += y[i][j] * y[i][j];
        }
        psum[(ty * 8 + i) * 17 + tx] = s;
        psq[(ty * 8 + i) * 17 + tx] = q;
    }
    __syncthreads();
    if (tid < BM) {
        float s = 0.f, q = 0.f;
        for (int t = 0; t < 16; t++) {
            s += psum[tid * 17 + t];
            q += psq[tid * 17 + t];
        }
        float mu = s * (1.f / D);
        float var = q * (1.f / D) - mu * mu;
        mu_s[tid] = mu;
        rs_s[tid] = rsqrtf(var + 1e-5f);
    }
    __syncthreads();
    float lg[8], lb[8];
#pragma unroll
    for (int j = 0; j < 8; j++) {
        lg[j] = Lng[tx * 8 + j];
        lb[j] = Lnb[tx * 8 + j];
    }
#pragma unroll
    for (int i = 0; i < 8; i++) {
        int r = ty * 8 + i;
        int row = m0 + r;
        if (row < NN) {
            float mu = mu_s[r], rs = rs_s[r];
            float o[8];
#pragma unroll
            for (int j = 0; j < 8; j++) {
                float v = (y[i][j] - mu) * rs * lg[j] + lb[j];
                o[j] = (v > 0.f) ? v : expm1f(v);
            }
            size_t base = (size_t)row * D + tx * 8;
            *(float4*)&hout[base] = make_float4(o[0], o[1], o[2], o[3]);
            *(float4*)&hout[base + 4] = make_float4(o[4], o[5], o[6], o[7]);
            if (write_x) {
                size_t xo = (size_t)row * KU + tx * 8;
                split_store4(o[0], o[1], o[2], o[3], &g_xhi[xo], &g_xlo[xo]);
                split_store4(o[4], o[5], o[6], o[7], &g_xhi[xo + 4], &g_xlo[xo + 4]);
            }
        }
    }
}

// ---------------- launch ----------------
extern "C" void kernel_launch(void* const* d_in, const int* in_sizes, int n_in,
                              void* d_out, int out_size) {
    const float* feat = (const float*)d_in[0];
    const int* src = (const int*)d_in[1];
    const int* dst = (const int*)d_in[2];
    const float* Mw = (const float*)d_in[3];
    const float* Mb = (const float*)d_in[4];
    const float* Uw = (const float*)d_in[5];
    const float* Ub = (const float*)d_in[6];
    const float* bn_g = (const float*)d_in[7];
    const float* bn_b = (const float*)d_in[8];
    const float* mix_w = (const float*)d_in[9];
    const float* mix_b = (const float*)d_in[10];
    const float* ln_g = (const float*)d_in[11];
    const float* ln_b = (const float*)d_in[12];

    cudaFuncSetAttribute(k_ugemm_mma, cudaFuncAttributeMaxDynamicSharedMemorySize, 2 * STG * 2);

    k_init<<<(NN + 255) / 256, 256>>>();
    k_hist<<<(NE + 255) / 256, 256>>>(dst);
    k_scan<<<1, 1024>>>();
    k_scatter<<<(ET + 255) / 256, 256>>>(src, dst);
    k_split_feat<<<(NN * 32 + 255) / 256, 256>>>(feat);
    k_split_w<<<(3 * D * KU / 4 + 255) / 256, 256>>>(Uw);

    for (int l = 0; l < 3; l++) {
        int isel = (l == 0) ? 0 : l;
        int osel = (l == 2) ? 3 : (l + 1);
        const float* Mw_l = Mw + (size_t)l * D * 2 * D;
        const float* Mb_l = Mb + (size_t)l * D;

        k_gemm_msg<<<dim3(MBLK, 2), 256>>>(isel, feat, Mw_l, Mb_l);
        k_agg<<<(NN * 32 + 255) / 256, 256>>>();
        k_ugemm_mma<<<MBLK, 256, 2 * STG * 2>>>(l, Ub + (size_t)l * D);
        k_bnstats<<<200, 256>>>();
        k_bnfinal<<<1, 128>>>(bn_g + (size_t)l * D, bn_b + (size_t)l * D);
        k_mixln<<<MBLK, 256>>>(isel, feat, mix_w + (size_t)l * D * D,
                               mix_b + (size_t)l * D, ln_g + (size_t)l * D,
                               ln_b + (size_t)l * D, osel, (float*)d_out,
                               (l < 2) ? 1 : 0);
    }
}

// round 6
// speedup vs baseline: 1.6089x; 1.0860x over previous
#include <cuda_runtime.h>
#include <cuda_bf16.h>
#include <stdint.h>
#include <math.h>

#define NN 50000
#define NE 400000
#define ET (NE + NN)
#define D 128
#define KU 1664
#define BM 128
#define BN 128
#define BK 16
#define MBLK ((NN + BM - 1) / BM)   // 391
#define NPAD 50048
#define KC 32
#define NCHU (KU / KC)               // 52
#define TILEB 16384                  // 128 rows * 128B (32 hi | 32 lo bf16)
#define STGB (2 * TILEB)             // X tile + W tile
#define NSTG 3
#define SMEMSZ (NSTG * STGB)         // 98304

// ---------------- scratch ----------------
__device__ float g_ac[(size_t)NN * 256];    // [a | c] per node
__device__ float g_u[(size_t)NN * D];       // pre-BN u
__device__ float g_h1[(size_t)NN * D];
__device__ float g_h2[(size_t)NN * D];
__device__ __nv_bfloat16 g_xhi[(size_t)NPAD * KU];  // X = [h | agg | agg*s1 | agg*s2] hi
__device__ __nv_bfloat16 g_xlo[(size_t)NPAD * KU];  // lo
__device__ __nv_bfloat16 g_whi[(size_t)3 * D * KU]; // Uw split hi
__device__ __nv_bfloat16 g_wlo[(size_t)3 * D * KU];
__device__ __nv_bfloat16 g_mwhi[3 * 256 * 128];     // [Ws;Wd] split hi
__device__ __nv_bfloat16 g_mwlo[3 * 256 * 128];
__device__ int   g_cnt[NN];
__device__ int   g_rowptr[NN + 1];
__device__ int   g_wofs[NN];
__device__ int   g_srcs[ET];
__device__ float g_colsum[D];
__device__ float g_colsq[D];
__device__ float g_bnscale[D];
__device__ float g_bnshift[D];

// ---------------- PTX helpers ----------------
__device__ __forceinline__ uint32_t smem_u32(const void* p) {
    uint32_t a;
    asm("{ .reg .u64 t; cvta.to.shared.u64 t, %1; cvt.u32.u64 %0, t; }" : "=r"(a) : "l"(p));
    return a;
}
__device__ __forceinline__ void cpa16(uint32_t s, const void* g) {
    asm volatile("cp.async.cg.shared.global [%0], [%1], 16;" :: "r"(s), "l"(g) : "memory");
}
__device__ __forceinline__ void ldm4(uint32_t a, uint32_t* r) {
    asm volatile("ldmatrix.sync.aligned.m8n8.x4.shared.b16 {%0,%1,%2,%3}, [%4];"
                 : "=r"(r[0]), "=r"(r[1]), "=r"(r[2]), "=r"(r[3]) : "r"(a));
}
__device__ __forceinline__ void mma16816(float* c, const uint32_t* a, const uint32_t* b) {
    asm volatile("mma.sync.aligned.m16n8k16.row.col.f32.bf16.bf16.f32 "
                 "{%0,%1,%2,%3}, {%4,%5,%6,%7}, {%8,%9}, {%0,%1,%2,%3};"
                 : "+f"(c[0]), "+f"(c[1]), "+f"(c[2]), "+f"(c[3])
                 : "r"(a[0]), "r"(a[1]), "r"(a[2]), "r"(a[3]), "r"(b[0]), "r"(b[1]));
}
#define CP_COMMIT() asm volatile("cp.async.commit_group;" ::: "memory")
#define CP_WAIT0()  asm volatile("cp.async.wait_group 0;" ::: "memory")
#define CP_WAIT1()  asm volatile("cp.async.wait_group 1;" ::: "memory")

// ---------------- bf16 split ----------------
struct __align__(8) bfq { __nv_bfloat162 a, b; };
__device__ __forceinline__ void split_store4(float x0, float x1, float x2, float x3,
                                             __nv_bfloat16* hp, __nv_bfloat16* lp) {
    __nv_bfloat162 h0 = __floats2bfloat162_rn(x0, x1);
    __nv_bfloat162 h1 = __floats2bfloat162_rn(x2, x3);
    __nv_bfloat162 l0 = __floats2bfloat162_rn(x0 - __low2float(h0), x1 - __high2float(h0));
    __nv_bfloat162 l1 = __floats2bfloat162_rn(x2 - __low2float(h1), x3 - __high2float(h1));
    bfq h; h.a = h0; h.b = h1;
    bfq l; l.a = l0; l.b = l1;
    *(bfq*)hp = h;
    *(bfq*)lp = l;
}

// ---------------- packed f32x2 helpers (mixln SIMT GEMM) ----------------
__device__ __forceinline__ unsigned long long pack2(float x) {
    unsigned long long r;
    asm("mov.b64 %0, {%1, %1};" : "=l"(r) : "f"(x));
    return r;
}
__device__ __forceinline__ void ffma2(unsigned long long& c, unsigned long long a,
                                      unsigned long long b) {
    asm("fma.rn.f32x2 %0, %1, %2, %0;" : "+l"(c) : "l"(a), "l"(b));
}
__device__ __forceinline__ float2 upk2(unsigned long long v) {
    float2 r;
    asm("mov.b64 {%0, %1}, %2;" : "=f"(r.x), "=f"(r.y) : "l"(v));
    return r;
}
__device__ __forceinline__ const float* pick_h(int sel, const float* feat) {
    return sel == 0 ? feat : (sel == 1 ? g_h1 : g_h2);
}

__device__ __forceinline__ void mm_tile(const float* As, const float* Ws,
                                        unsigned long long acc[8][4], int tx, int ty) {
#pragma unroll
    for (int kk = 0; kk < BK; kk++) {
        unsigned long long b2[4];
#pragma unroll
        for (int j = 0; j < 4; j++)
            b2[j] = *(const unsigned long long*)&Ws[kk * BN + tx * 8 + j * 2];
#pragma unroll
        for (int i = 0; i < 8; i++) {
            unsigned long long a2 = pack2(As[kk * BM + ty * 8 + i]);
#pragma unroll
            for (int j = 0; j < 4; j++) ffma2(acc[i][j], a2, b2[j]);
        }
    }
}

// ---------------- mma mainloop (3-stage cp.async pipeline, swizzled smem) ----------------
__device__ __forceinline__ void mma_issue_tile(const __nv_bfloat16* ph, const __nv_bfloat16* pl,
                                               int ld, int kg, uint32_t dstbase, int tid) {
    int row = tid >> 1, sel = tid & 1;
    const __nv_bfloat16* src = (sel ? pl : ph) + (size_t)row * ld + kg;
    uint32_t rb = dstbase + row * 128;
    int r7 = row & 7;
#pragma unroll
    for (int j = 0; j < 4; j++) {
        int chunk = (sel * 4 + j) ^ r7;
        cpa16(rb + chunk * 16, src + j * 8);
    }
}

__device__ __forceinline__ void mma_mainloop(const __nv_bfloat16* axh, const __nv_bfloat16* axl,
                                             int lda,
                                             const __nv_bfloat16* bwh, const __nv_bfloat16* bwl,
                                             int ldb, int nch, uint32_t smb, int tid,
                                             float acc[2][2][4][4]) {
    int wid = tid >> 5, l = tid & 31;
    int wm = wid >> 1, wn = wid & 1;
    // prologue: chunks 0,1
#pragma unroll
    for (int p = 0; p < 2; p++) {
        uint32_t sb = smb + p * STGB;
        mma_issue_tile(axh, axl, lda, p * KC, sb, tid);
        mma_issue_tile(bwh, bwl, ldb, p * KC, sb + TILEB, tid);
        CP_COMMIT();
    }
    for (int c = 0; c < nch; c++) {
        if (c == nch - 1) { CP_WAIT0(); } else { CP_WAIT1(); }
        __syncthreads();
        if (c + 2 < nch) {
            uint32_t sb = smb + ((c + 2) % NSTG) * STGB;
            mma_issue_tile(axh, axl, lda, (c + 2) * KC, sb, tid);
            mma_issue_tile(bwh, bwl, ldb, (c + 2) * KC, sb + TILEB, tid);
            CP_COMMIT();
        }
        uint32_t st = smb + (c % NSTG) * STGB;
#pragma unroll
        for (int kk = 0; kk < 2; kk++) {
            uint32_t ah[2][4], al[2][4];
#pragma unroll
            for (int mf = 0; mf < 2; mf++) {
                int arow = wm * 32 + mf * 16 + (l & 7) + ((l >> 3) & 1) * 8;
                int ch = kk * 2 + (l >> 4);
                uint32_t base = st + arow * 128;
                int r7 = arow & 7;
                ldm4(base + ((ch ^ r7) * 16), ah[mf]);
                ldm4(base + (((ch + 4) ^ r7) * 16), al[mf]);
            }
#pragma unroll
            for (int nh = 0; nh < 2; nh++) {
                uint32_t bh[2][4], bl[2][4];
#pragma unroll
                for (int g16 = 0; g16 < 2; g16++) {
                    int brow = wn * 64 + nh * 32 + g16 * 16 + (l & 7) + (l >> 4) * 8;
                    int ch = kk * 2 + ((l >> 3) & 1);
                    uint32_t base = st + TILEB + brow * 128;
                    int r7 = brow & 7;
                    ldm4(base + ((ch ^ r7) * 16), bh[g16]);
                    ldm4(base + (((ch + 4) ^ r7) * 16), bl[g16]);
                }
#pragma unroll
                for (int mf = 0; mf < 2; mf++)
#pragma unroll
                    for (int g16 = 0; g16 < 2; g16++)
#pragma unroll
                        for (int f = 0; f < 2; f++) {
                            float* c4p = acc[mf][nh][g16 * 2 + f];
                            mma16816(c4p, ah[mf], &bh[g16][f * 2]);   // hi*hi
                            mma16816(c4p, ah[mf], &bl[g16][f * 2]);   // hi*lo
                            mma16816(c4p, al[mf], &bh[g16][f * 2]);   // lo*hi
                        }
            }
        }
    }
}

// ---------------- setup kernels ----------------
__global__ void k_init() {
    int i = blockIdx.x * blockDim.x + threadIdx.x;
    if (i < NN) g_cnt[i] = 1;
    if (i < D) { g_colsum[i] = 0.f; g_colsq[i] = 0.f; }
}

__global__ void k_hist(const int* __restrict__ dst) {
    int e = blockIdx.x * blockDim.x + threadIdx.x;
    if (e < NE) atomicAdd(&g_cnt[dst[e]], 1);
}

__global__ void k_scan() {
    __shared__ int sd[1024];
    __shared__ int s_run;
    int tid = threadIdx.x;
    if (tid == 0) { s_run = 0; g_rowptr[0] = 0; }
    __syncthreads();
    for (int base = 0; base < NN; base += 1024) {
        int i = base + tid;
        int v = (i < NN) ? g_cnt[i] : 0;
        sd[tid] = v;
        __syncthreads();
        for (int off = 1; off < 1024; off <<= 1) {
            int t = (tid >= off) ? sd[tid - off] : 0;
            __syncthreads();
            sd[tid] += t;
            __syncthreads();
        }
        int inc = sd[tid] + s_run;
        if (i < NN) { g_rowptr[i + 1] = inc; g_wofs[i] = inc - v; }
        __syncthreads();
        if (tid == 1023) s_run += sd[1023];
        __syncthreads();
    }
}

__global__ void k_scatter(const int* __restrict__ src, const int* __restrict__ dst) {
    int i = blockIdx.x * blockDim.x + threadIdx.x;
    if (i >= ET) return;
    int d, s;
    if (i < NE) { d = dst[i]; s = src[i]; }
    else        { d = i - NE; s = d; }
    int p = atomicAdd(&g_wofs[d], 1);
    g_srcs[p] = s;
}

__global__ void k_split_feat(const float* __restrict__ feat) {
    int i = blockIdx.x * blockDim.x + threadIdx.x;
    if (i >= NN * 32) return;
    int r = i >> 5;
    int c = (i & 31) * 4;
    float4 v = *(const float4*)&feat[(size_t)r * D + c];
    split_store4(v.x, v.y, v.z, v.w, &g_xhi[(size_t)r * KU + c], &g_xlo[(size_t)r * KU + c]);
}

__global__ void k_split_w(const float* __restrict__ Uw) {
    int i = blockIdx.x * blockDim.x + threadIdx.x;
    if (i >= 3 * D * KU / 4) return;
    size_t o = (size_t)i * 4;
    float4 v = *(const float4*)&Uw[o];
    split_store4(v.x, v.y, v.z, v.w, &g_whi[o], &g_wlo[o]);
}

// build B for msg GEMM: rows 0..127 = Ws (Mw[:, :128]), rows 128..255 = Wd (Mw[:, 128:])
__global__ void k_split_mw(const float* __restrict__ Mw) {
    int i = blockIdx.x * blockDim.x + threadIdx.x;
    if (i >= 3 * 256 * 128 / 4) return;
    size_t o = (size_t)i * 4;
    int k = (int)(o & 127);
    int n = (int)((o >> 7) & 255);
    int l = (int)(o >> 15);
    const float* src;
    if (n < 128) src = Mw + ((size_t)l * 128 + n) * 256 + k;
    else         src = Mw + ((size_t)l * 128 + (n - 128)) * 256 + 128 + k;
    float4 v = *(const float4*)src;
    split_store4(v.x, v.y, v.z, v.w, &g_mwhi[o], &g_mwlo[o]);
}

// ---------------- msg GEMM (mma): g_ac = h @ [Ws|Wd]^T (+Mb on c half) ----------------
__global__ __launch_bounds__(256, 2) void k_msg_mma(int layer, const float* __restrict__ Mb) {
    extern __shared__ char sm[];
    uint32_t smb = smem_u32(sm);
    int tid = threadIdx.x, wid = tid >> 5, l = tid & 31;
    int wm = wid >> 1, wn = wid & 1;
    int m0 = blockIdx.x * BM;
    int half = blockIdx.y;

    const __nv_bfloat16* axh = g_xhi + (size_t)m0 * KU;
    const __nv_bfloat16* axl = g_xlo + (size_t)m0 * KU;
    const __nv_bfloat16* bwh = g_mwhi + ((size_t)layer * 256 + half * 128) * 128;
    const __nv_bfloat16* bwl = g_mwlo + ((size_t)layer * 256 + half * 128) * 128;

    float acc[2][2][4][4];
#pragma unroll
    for (int a = 0; a < 2; a++)
#pragma unroll
        for (int b = 0; b < 2; b++)
#pragma unroll
            for (int c = 0; c < 4; c++)
#pragma unroll
                for (int d = 0; d < 4; d++) acc[a][b][c][d] = 0.f;

    mma_mainloop(axh, axl, KU, bwh, bwl, 128, 4, smb, tid, acc);

    int grp = l >> 2, tig = l & 3;
#pragma unroll
    for (int mf = 0; mf < 2; mf++) {
        int r0 = m0 + wm * 32 + mf * 16 + grp;
#pragma unroll
        for (int nh = 0; nh < 2; nh++)
#pragma unroll
            for (int nf = 0; nf < 4; nf++) {
                int col = wn * 64 + nh * 32 + nf * 8 + tig * 2;
                float b0 = half ? Mb[col] : 0.f;
                float b1 = half ? Mb[col + 1] : 0.f;
                float* a4 = acc[mf][nh][nf];
                size_t cb = (size_t)half * 128 + col;
                if (r0 < NN)
                    *(float2*)&g_ac[(size_t)r0 * 256 + cb] = make_float2(a4[0] + b0, a4[1] + b1);
                if (r0 + 8 < NN)
                    *(float2*)&g_ac[(size_t)(r0 + 8) * 256 + cb] = make_float2(a4[2] + b0, a4[3] + b1);
            }
    }
}

// ---------------- edge aggregation: 1 warp per node; emits bf16 hi/lo X cols 128..1663 ----------------
__global__ void k_agg() {
    int gw = (blockIdx.x * blockDim.x + threadIdx.x) >> 5;
    int lane = threadIdx.x & 31;
    if (gw >= NN) return;
    int v = gw;
    int c4 = lane * 4;
    float4 cv = *(const float4*)&g_ac[(size_t)v * 256 + 128 + c4];
    float c[4] = {cv.x, cv.y, cv.z, cv.w};
    float sum[4] = {0.f, 0.f, 0.f, 0.f};
    float sq[4] = {0.f, 0.f, 0.f, 0.f};
    float mx[4] = {-1e30f, -1e30f, -1e30f, -1e30f};
    float mn[4] = {1e30f, 1e30f, 1e30f, 1e30f};
    int e0 = g_rowptr[v], e1 = g_rowptr[v + 1];
    for (int e = e0; e < e1; e++) {
        int s = g_srcs[e];
        float4 av = *(const float4*)&g_ac[(size_t)s * 256 + c4];
        float a[4] = {av.x, av.y, av.z, av.w};
#pragma unroll
        for (int j = 0; j < 4; j++) {
            float m = a[j] + c[j];
            sum[j] += m;
            sq[j] += m * m;
            mx[j] = fmaxf(mx[j], m);
            mn[j] = fminf(mn[j], m);
        }
    }
    float deg = (float)(e1 - e0);
    float inv = 1.f / deg;
    float st[4], vr[4];
#pragma unroll
    for (int j = 0; j < 4; j++) {
        float mean = sum[j] * inv;
        float var = fmaxf(sq[j] * inv - mean * mean, 0.f);
        vr[j] = var;
        st[j] = sqrtf(var + 1e-30f);
    }
    float ld = logf(deg + 1.f);
    float s1v = ld * 0.25f;
    float s2v = 4.f / ld;
    size_t xb = (size_t)v * KU;
#pragma unroll
    for (int g = 0; g < 3; g++) {
        float sc = (g == 0) ? 1.f : (g == 1 ? s1v : s2v);
        int base = 128 + g * 512 + c4;
        split_store4(mx[0] * sc, mx[1] * sc, mx[2] * sc, mx[3] * sc,
                     &g_xhi[xb + base], &g_xlo[xb + base]);
        split_store4(mn[0] * sc, mn[1] * sc, mn[2] * sc, mn[3] * sc,
                     &g_xhi[xb + base + 128], &g_xlo[xb + base + 128]);
        split_store4(st[0] * sc, st[1] * sc, st[2] * sc, st[3] * sc,
                     &g_xhi[xb + base + 256], &g_xlo[xb + base + 256]);
        split_store4(vr[0] * sc, vr[1] * sc, vr[2] * sc, vr[3] * sc,
                     &g_xhi[xb + base + 384], &g_xlo[xb + base + 384]);
    }
}

// ---------------- U GEMM (mma) + BN column stats in epilogue ----------------
__global__ __launch_bounds__(256, 2) void k_ugemm_mma(int layer, const float* __restrict__ Ub) {
    extern __shared__ char sm[];
    uint32_t smb = smem_u32(sm);
    int tid = threadIdx.x, wid = tid >> 5, l = tid & 31;
    int wm = wid >> 1, wn = wid & 1;
    int m0 = blockIdx.x * BM;

    const __nv_bfloat16* axh = g_xhi + (size_t)m0 * KU;
    const __nv_bfloat16* axl = g_xlo + (size_t)m0 * KU;
    const __nv_bfloat16* bwh = g_whi + (size_t)layer * D * KU;
    const __nv_bfloat16* bwl = g_wlo + (size_t)layer * D * KU;

    float acc[2][2][4][4];
#pragma unroll
    for (int a = 0; a < 2; a++)
#pragma unroll
        for (int b = 0; b < 2; b++)
#pragma unroll
            for (int c = 0; c < 4; c++)
#pragma unroll
                for (int d = 0; d < 4; d++) acc[a][b][c][d] = 0.f;

    mma_mainloop(axh, axl, KU, bwh, bwl, KU, NCHU, smb, tid, acc);

    __syncthreads();
    float* cs_s = (float*)sm;
    float* cq_s = cs_s + 128;
    if (tid < 128) { cs_s[tid] = 0.f; cq_s[tid] = 0.f; }
    __syncthreads();

    const float RSQN = 0.004472135954999579f;  // sqrt(1/50000)
    int grp = l >> 2, tig = l & 3;
    float cs[16], cq[16];
#pragma unroll
    for (int t = 0; t < 16; t++) { cs[t] = 0.f; cq[t] = 0.f; }

#pragma unroll
    for (int mf = 0; mf < 2; mf++) {
        int r0 = m0 + wm * 32 + mf * 16 + grp;
        bool v0 = r0 < NN, v1 = (r0 + 8) < NN;
#pragma unroll
        for (int nh = 0; nh < 2; nh++)
#pragma unroll
            for (int nf = 0; nf < 4; nf++) {
                int col = wn * 64 + nh * 32 + nf * 8 + tig * 2;
                float u0 = Ub[col], u1 = Ub[col + 1];
                float* a4 = acc[mf][nh][nf];
                int idx = nh * 8 + nf * 2;
                if (v0) {
                    float o0 = (a4[0] + u0) * RSQN;
                    float o1 = (a4[1] + u1) * RSQN;
                    *(float2*)&g_u[(size_t)r0 * D + col] = make_float2(o0, o1);
                    cs[idx] += o0; cq[idx] += o0 * o0;
                    cs[idx + 1] += o1; cq[idx + 1] += o1 * o1;
                }
                if (v1) {
                    float o2 = (a4[2] + u0) * RSQN;
                    float o3 = (a4[3] + u1) * RSQN;
                    *(float2*)&g_u[(size_t)(r0 + 8) * D + col] = make_float2(o2, o3);
                    cs[idx] += o2; cq[idx] += o2 * o2;
                    cs[idx + 1] += o3; cq[idx + 1] += o3 * o3;
                }
            }
    }
    // reduce over grp (lane bits 2..4) via xor shuffles
#pragma unroll
    for (int t = 0; t < 16; t++) {
        float s = cs[t], q = cq[t];
        s += __shfl_xor_sync(0xFFFFFFFF, s, 4);
        s += __shfl_xor_sync(0xFFFFFFFF, s, 8);
        s += __shfl_xor_sync(0xFFFFFFFF, s, 16);
        q += __shfl_xor_sync(0xFFFFFFFF, q, 4);
        q += __shfl_xor_sync(0xFFFFFFFF, q, 8);
        q += __shfl_xor_sync(0xFFFFFFFF, q, 16);
        cs[t] = s; cq[t] = q;
    }
    if (l < 4) {  // grp == 0 lanes; tig == l
#pragma unroll
        for (int nh = 0; nh < 2; nh++)
#pragma unroll
            for (int nf = 0; nf < 4; nf++) {
                int col = wn * 64 + nh * 32 + nf * 8 + l * 2;
                int idx = nh * 8 + nf * 2;
                atomicAdd(&cs_s[col], cs[idx]);
                atomicAdd(&cs_s[col + 1], cs[idx + 1]);
                atomicAdd(&cq_s[col], cq[idx]);
                atomicAdd(&cq_s[col + 1], cq[idx + 1]);
            }
    }
    __syncthreads();
    if (tid < 128) {
        atomicAdd(&g_colsum[tid], cs_s[tid]);
        atomicAdd(&g_colsq[tid], cq_s[tid]);
    }
}

__global__ void k_bnfinal(const float* __restrict__ bng, const float* __restrict__ bnb) {
    int c = threadIdx.x;
    if (c < D) {
        float mu = g_colsum[c] * (1.f / NN);
        float var = g_colsq[c] * (1.f / NN) - mu * mu;
        float inv = rsqrtf(var + 1e-5f);
        float sc = inv * bng[c];
        g_bnscale[c] = sc;
        g_bnshift[c] = bnb[c] - mu * sc;
        g_colsum[c] = 0.f;
        g_colsq[c] = 0.f;
    }
}

// ---------------- mix GEMM + leaky + residual + LayerNorm + ELU (+ X h-cols) ----------------
__global__ __launch_bounds__(256) void k_mixln(int in_sel, const float* __restrict__ feat,
                                               const float* __restrict__ Mixw,
                                               const float* __restrict__ Mixb,
                                               const float* __restrict__ Lng,
                                               const float* __restrict__ Lnb,
                                               int out_sel, float* __restrict__ dout,
                                               int write_x) {
    const float* hin = pick_h(in_sel, feat);
    float* hout = (out_sel == 1) ? g_h1 : (out_sel == 2 ? g_h2 : dout);
    __shared__ float pool[4352];
    __shared__ float bs_s[D], bh_s[D];
    __shared__ float mu_s[BM], rs_s[BM];
    float* As = pool;
    float* Ws = pool + BK * BM;
    int m0 = blockIdx.x * BM;
    int tid = threadIdx.x, tx = tid & 15, ty = tid >> 4;
    if (tid < D) { bs_s[tid] = g_bnscale[tid]; bh_s[tid] = g_bnshift[tid]; }
    __syncthreads();
    unsigned long long acc[8][4];
#pragma unroll
    for (int i = 0; i < 8; i++)
#pragma unroll
        for (int j = 0; j < 4; j++) acc[i][j] = 0ull;

    for (int k0 = 0; k0 < D; k0 += BK) {
#pragma unroll
        for (int i = 0; i < 2; i++) {
            int q = tid * 2 + i;
            int m = q >> 2;
            int kq = (q & 3) * 4;
            int row = m0 + m;
            float4 v = make_float4(0.f, 0.f, 0.f, 0.f);
            if (row < NN) {
                v = *(const float4*)&g_u[(size_t)row * D + k0 + kq];
                v.x = v.x * bs_s[k0 + kq + 0] + bh_s[k0 + kq + 0];
                v.y = v.y * bs_s[k0 + kq + 1] + bh_s[k0 + kq + 1];
                v.z = v.z * bs_s[k0 + kq + 2] + bh_s[k0 + kq + 2];
                v.w = v.w * bs_s[k0 + kq + 3] + bh_s[k0 + kq + 3];
            }
            As[(kq + 0) * BM + m] = v.x;
            As[(kq + 1) * BM + m] = v.y;
            As[(kq + 2) * BM + m] = v.z;
            As[(kq + 3) * BM + m] = v.w;
            float4 w = *(const float4*)&Mixw[(size_t)m * D + k0 + kq];
            Ws[(kq + 0) * BN + m] = w.x;
            Ws[(kq + 1) * BN + m] = w.y;
            Ws[(kq + 2) * BN + m] = w.z;
            Ws[(kq + 3) * BN + m] = w.w;
        }
        __syncthreads();
        mm_tile(As, Ws, acc, tx, ty);
        __syncthreads();
    }
    float y[8][8];
    {
        float mb[8];
#pragma unroll
        for (int j = 0; j < 8; j++) mb[j] = Mixb[tx * 8 + j];
#pragma unroll
        for (int i = 0; i < 8; i++) {
#pragma unroll
            for (int j = 0; j < 4; j++) {
                float2 p = upk2(acc[i][j]);
                y[i][2 * j] = p.x + mb[2 * j];
                y[i][2 * j + 1] = p.y + mb[2 * j + 1];
            }
#pragma unroll
            for (int j = 0; j < 8; j++) {
                float t = y[i][j];
                y[i][j] = fmaxf(t, 0.01f * t);
            }
            int row = m0 + ty * 8 + i;
            if (row < NN) {
                float4 h0 = *(const float4*)&hin[(size_t)row * D + tx * 8];
                float4 h1 = *(const float4*)&hin[(size_t)row * D + tx * 8 + 4];
                y[i][0] += h0.x; y[i][1] += h0.y; y[i][2] += h0.z; y[i][3] += h0.w;
                y[i][4] += h1.x; y[i][5] += h1.y; y[i][6] += h1.z; y[i][7] += h1.w;
            }
        }
    }
    float* psum = pool;
    float* psq = pool + 128 * 17;
#pragma unroll
    for (int i = 0; i < 8; i++) {
        float s = 0.f, q = 0.f;
#pragma unroll
        for (int j = 0; j < 8; j++) {
            s += y[i][j];
            q += y[i][j] * y[i][j];
        }
        psum[(ty * 8 + i) * 17 + tx] = s;
        psq[(ty * 8 + i) * 17 + tx] = q;
    }
    __syncthreads();
    if (tid < BM) {
        float s = 0.f, q = 0.f;
        for (int t = 0; t < 16; t++) {
            s += psum[tid * 17 + t];
            q += psq[tid * 17 + t];
        }
        float mu = s * (1.f / D);
        float var = q * (1.f / D) - mu * mu;
        mu_s[tid] = mu;
        rs_s[tid] = rsqrtf(var + 1e-5f);
    }
    __syncthreads();
    float lg[8], lb[8];
#pragma unroll
    for (int j = 0; j < 8; j++) {
        lg[j] = Lng[tx * 8 + j];
        lb[j] = Lnb[tx * 8 + j];
    }
#pragma unroll
    for (int i = 0; i < 8; i++) {
        int r = ty * 8 + i;
        int row = m0 + r;
        if (row < NN) {
            float mu = mu_s[r], rs = rs_s[r];
            float o[8];
#pragma unroll
            for (int j = 0; j < 8; j++) {
                float v = (y[i][j] - mu) * rs * lg[j] + lb[j];
                o[j] = (v > 0.f) ? v : expm1f(v);
            }
            size_t base = (size_t)row * D + tx * 8;
            *(float4*)&hout[base] = make_float4(o[0], o[1], o[2], o[3]);
            *(float4*)&hout[base + 4] = make_float4(o[4], o[5], o[6], o[7]);
            if (write_x) {
                size_t xo = (size_t)row * KU + tx * 8;
                split_store4(o[0], o[1], o[2], o[3], &g_xhi[xo], &g_xlo[xo]);
                split_store4(o[4], o[5], o[6], o[7], &g_xhi[xo + 4], &g_xlo[xo + 4]);
            }
        }
    }
}

// ---------------- launch ----------------
extern "C" void kernel_launch(void* const* d_in, const int* in_sizes, int n_in,
                              void* d_out, int out_size) {
    const float* feat = (const float*)d_in[0];
    const int* src = (const int*)d_in[1];
    const int* dst = (const int*)d_in[2];
    const float* Mw = (const float*)d_in[3];
    const float* Mb = (const float*)d_in[4];
    const float* Uw = (const float*)d_in[5];
    const float* Ub = (const float*)d_in[6];
    const float* bn_g = (const float*)d_in[7];
    const float* bn_b = (const float*)d_in[8];
    const float* mix_w = (const float*)d_in[9];
    const float* mix_b = (const float*)d_in[10];
    const float* ln_g = (const float*)d_in[11];
    const float* ln_b = (const float*)d_in[12];

    cudaFuncSetAttribute(k_ugemm_mma, cudaFuncAttributeMaxDynamicSharedMemorySize, SMEMSZ);
    cudaFuncSetAttribute(k_msg_mma, cudaFuncAttributeMaxDynamicSharedMemorySize, SMEMSZ);

    k_init<<<(NN + 255) / 256, 256>>>();
    k_hist<<<(NE + 255) / 256, 256>>>(dst);
    k_scan<<<1, 1024>>>();
    k_scatter<<<(ET + 255) / 256, 256>>>(src, dst);
    k_split_feat<<<(NN * 32 + 255) / 256, 256>>>(feat);
    k_split_w<<<(3 * D * KU / 4 + 255) / 256, 256>>>(Uw);
    k_split_mw<<<(3 * 256 * 128 / 4 + 255) / 256, 256>>>(Mw);

    for (int l = 0; l < 3; l++) {
        int isel = (l == 0) ? 0 : l;
        int osel = (l == 2) ? 3 : (l + 1);

        k_msg_mma<<<dim3(MBLK, 2), 256, SMEMSZ>>>(l, Mb + (size_t)l * D);
        k_agg<<<(NN * 32 + 255) / 256, 256>>>();
        k_ugemm_mma<<<MBLK, 256, SMEMSZ>>>(l, Ub + (size_t)l * D);
        k_bnfinal<<<1, 128>>>(bn_g + (size_t)l * D, bn_b + (size_t)l * D);
        k_mixln<<<MBLK, 256>>>(isel, feat, mix_w + (size_t)l * D * D,
                               mix_b + (size_t)l * D, ln_g + (size_t)l * D,
                               ln_b + (size_t)l * D, osel, (float*)d_out,
                               (l < 2) ? 1 : 0);
    }
}